// round 17
// baseline (speedup 1.0000x reference)
#include <cuda_runtime.h>
#include <math.h>

#define NPTS 262144
#define CH   256
#define NB   8
#define ROWS 32
#define HALO (ROWS + 2)
#define MCHUNK 32
#define EPSV 1e-5f

typedef unsigned long long u64;

// scratch (no allocations allowed; __device__ globals are the sanctioned path)
__device__ int    g_off[NB + 1];
__device__ float  g_part[NB * MCHUNK][3];
__device__ float  g_cw[4 * CH];    // centered, gamma-folded weights: [cwx|cwy|cwz|cb]
__device__ float  g_quad[10];      // var quadratic form coefficients

// ---- packed f32x2 helpers (sm_103a FFMA2 path; ptxas never emits these itself)
__device__ __forceinline__ u64 pk(float a, float b) {
    u64 r; asm("mov.b64 %0, {%1, %2};" : "=l"(r) : "f"(a), "f"(b)); return r;
}
__device__ __forceinline__ void upk(u64 v, float& a, float& b) {
    asm("mov.b64 {%0, %1}, %2;" : "=f"(a), "=f"(b) : "l"(v));
}
__device__ __forceinline__ u64 fma2(u64 a, u64 b, u64 c) {
    u64 r; asm("fma.rn.f32x2 %0, %1, %2, %3;" : "=l"(r) : "l"(a), "l"(b), "l"(c)); return r;
}
__device__ __forceinline__ u64 add2(u64 a, u64 b) {
    u64 r; asm("add.rn.f32x2 %0, %1, %2;" : "=l"(r) : "l"(a), "l"(b)); return r;
}
__device__ __forceinline__ u64 mul2(u64 a, u64 b) {
    u64 r; asm("mul.rn.f32x2 %0, %1, %2;" : "=l"(r) : "l"(a), "l"(b)); return r;
}

__device__ __forceinline__ void warp_sum2(float& a, float& b) {
#pragma unroll
    for (int o = 16; o > 0; o >>= 1) {
        a += __shfl_xor_sync(0xffffffffu, a, o);
        b += __shfl_xor_sync(0xffffffffu, b, o);
    }
}

__device__ __forceinline__ float warp_sum_f(float v) {
#pragma unroll
    for (int o = 16; o > 0; o >>= 1) v += __shfl_xor_sync(0xffffffffu, v, o);
    return v;
}

__device__ __forceinline__ float tanh_a(float u) {
    float t; asm("tanh.approx.f32 %0, %1;" : "=f"(t) : "f"(u)); return t;
}

// dtype-sniffed local prefix decode (lengths may be int32 or int64)
__device__ __forceinline__ void decode_offsets(const void* lengths_raw, int* off) {
    const int* l32 = (const int*)lengths_raw;
    long long v[NB];
    long long s32 = 0;
#pragma unroll
    for (int i = 0; i < NB; i++) s32 += l32[i];
    if (s32 == (long long)NPTS) {
#pragma unroll
        for (int i = 0; i < NB; i++) v[i] = l32[i];
    } else {
        const long long* l64 = (const long long*)lengths_raw;
#pragma unroll
        for (int i = 0; i < NB; i++) v[i] = l64[i];
    }
    long long acc = 0;
    off[0] = 0;
#pragma unroll
    for (int i = 0; i < NB; i++) {
        acc += v[i];
        long long c = acc < 0 ? 0 : (acc > NPTS ? NPTS : acc);
        off[i + 1] = (int)c;
    }
    off[NB] = NPTS;
}

// ---------------------------------------------------------------- k_pre
__global__ void __launch_bounds__(256) k_pre(
    const void* __restrict__ lengths_raw, const float* __restrict__ coord,
    const float* __restrict__ w_xyz, const float* __restrict__ b_xyz,
    const float* __restrict__ g1)
{
    const int tid = threadIdx.x;
    const int lane = tid & 31, w = tid >> 5;

    if (blockIdx.x < NB * MCHUNK) {
        __shared__ int s_off[NB + 1];
        if (tid == 0) decode_offsets(lengths_raw, s_off);
        __syncthreads();
        const int b = blockIdx.x / MCHUNK;
        const int chunk = blockIdx.x % MCHUNK;
        const int s = s_off[b], e = s_off[b + 1];
        const int len = e - s;
        const int cs = s + (int)(((long long)len * chunk) / MCHUNK);
        const int ce = s + (int)(((long long)len * (chunk + 1)) / MCHUNK);

        float sx = 0.f, sy = 0.f, sz = 0.f;
        for (int i = cs + tid; i < ce; i += 256) {
            sx += coord[(size_t)i * 3 + 0];
            sy += coord[(size_t)i * 3 + 1];
            sz += coord[(size_t)i * 3 + 2];
        }
        sx = warp_sum_f(sx); sy = warp_sum_f(sy); sz = warp_sum_f(sz);
        __shared__ float red[8][3];
        if (lane == 0) { red[w][0] = sx; red[w][1] = sy; red[w][2] = sz; }
        __syncthreads();
        if (tid < 3) {
            float a = 0.f;
#pragma unroll
            for (int i = 0; i < 8; i++) a += red[i][tid];
            g_part[blockIdx.x][tid] = a;
        }
        return;
    }

    // ---- weight precompute block
    __shared__ float red[8][10];
    __shared__ float s_mw[4];

    if (tid == 0) {
        int off[NB + 1];
        decode_offsets(lengths_raw, off);
#pragma unroll
        for (int i = 0; i <= NB; i++) g_off[i] = off[i];
    }

    const float wx = w_xyz[0 * CH + tid];
    const float wy = w_xyz[1 * CH + tid];
    const float wz = w_xyz[2 * CH + tid];
    const float bx = b_xyz[tid];
    float m0 = warp_sum_f(wx), m1 = warp_sum_f(wy), m2 = warp_sum_f(wz), m3 = warp_sum_f(bx);
    if (lane == 0) { red[w][0] = m0; red[w][1] = m1; red[w][2] = m2; red[w][3] = m3; }
    __syncthreads();
    if (tid < 4) {
        float a = 0.f;
#pragma unroll
        for (int i = 0; i < 8; i++) a += red[i][tid];
        s_mw[tid] = a * (1.f / CH);
    }
    __syncthreads();

    const float ax = wx - s_mw[0], ay = wy - s_mw[1], az = wz - s_mw[2], ab = bx - s_mw[3];
    const float gch = g1[tid];
    g_cw[0 * CH + tid] = ax * gch;
    g_cw[1 * CH + tid] = ay * gch;
    g_cw[2 * CH + tid] = az * gch;
    g_cw[3 * CH + tid] = ab * gch;

    float q[10] = {ax*ax, ay*ay, az*az, ax*ay, ax*az, ay*az, ax*ab, ay*ab, az*ab, ab*ab};
#pragma unroll
    for (int i = 0; i < 10; i++) q[i] = warp_sum_f(q[i]);
    if (lane == 0) {
#pragma unroll
        for (int i = 0; i < 10; i++) red[w][i] = q[i];
    }
    __syncthreads();
    if (tid < 10) {
        float a = 0.f;
#pragma unroll
        for (int i = 0; i < 8; i++) a += red[i][tid];
        a *= (1.f / CH);
        if (tid >= 3 && tid <= 8) a *= 2.f;   // fold 2x into cross terms
        g_quad[tid] = a;
    }
}

// ---------------------------------------------------------------- k_main
// R9 structure (strided rows for ILP) + packed f32x2 channel math.
__global__ void __launch_bounds__(256, 3) k_main(
    const float* __restrict__ feat, const float* __restrict__ coord,
    const float* __restrict__ be1,
    const float* __restrict__ w_conv, const float* __restrict__ b_conv,
    const float* __restrict__ g2, const float* __restrict__ be2,
    float* __restrict__ out)
{
    __shared__ float sf[HALO][CH];
    __shared__ int   s_off[NB + 1];
    __shared__ float s_mean[NB][3];
    __shared__ float s_q[10];

    const int tid  = threadIdx.x;
    const int lane = tid & 31;
    const int warp = tid >> 5;
    const int c0   = lane * 4;
    const int c1   = c0 + 128;
    const int r0   = blockIdx.x * ROWS;

    if (tid <= NB) s_off[tid] = g_off[tid];
    if (tid >= 16 && tid < 26) s_q[tid - 16] = g_quad[tid - 16];
    if (tid >= 32 && tid < 32 + NB * 3) {
        const int b = (tid - 32) / 3, d = (tid - 32) % 3;
        float a = 0.f;
#pragma unroll
        for (int i = 0; i < MCHUNK; i++) a += g_part[b * MCHUNK + i][d];
        const int len = g_off[b + 1] - g_off[b];
        s_mean[b][d] = a / (float)(len > 0 ? len : 1);
    }
    __syncthreads();

    // ---- phase-1 params packed: pair p covers channels {2p, 2p+1} of the lane's 8
    u64 cwx2[4], cwy2[4], cwz2[4], cbv2[4], bb2[4];
    {
        const float4 a0 = *(const float4*)&g_cw[0 * CH + c0], a1 = *(const float4*)&g_cw[0 * CH + c1];
        const float4 b0 = *(const float4*)&g_cw[1 * CH + c0], b1 = *(const float4*)&g_cw[1 * CH + c1];
        const float4 e0 = *(const float4*)&g_cw[2 * CH + c0], e1 = *(const float4*)&g_cw[2 * CH + c1];
        const float4 d0 = *(const float4*)&g_cw[3 * CH + c0], d1 = *(const float4*)&g_cw[3 * CH + c1];
        const float4 f0 = *(const float4*)&be1[c0],           f1 = *(const float4*)&be1[c1];
        cwx2[0] = pk(a0.x, a0.y); cwx2[1] = pk(a0.z, a0.w); cwx2[2] = pk(a1.x, a1.y); cwx2[3] = pk(a1.z, a1.w);
        cwy2[0] = pk(b0.x, b0.y); cwy2[1] = pk(b0.z, b0.w); cwy2[2] = pk(b1.x, b1.y); cwy2[3] = pk(b1.z, b1.w);
        cwz2[0] = pk(e0.x, e0.y); cwz2[1] = pk(e0.z, e0.w); cwz2[2] = pk(e1.x, e1.y); cwz2[3] = pk(e1.z, e1.w);
        cbv2[0] = pk(d0.x, d0.y); cbv2[1] = pk(d0.z, d0.w); cbv2[2] = pk(d1.x, d1.y); cbv2[3] = pk(d1.z, d1.w);
        bb2[0]  = pk(f0.x, f0.y); bb2[1]  = pk(f0.z, f0.w); bb2[2]  = pk(f1.x, f1.y); bb2[3]  = pk(f1.z, f1.w);
    }
    const u64 GC0 = pk(0.0356774081f, 0.0356774081f);
    const u64 GC1 = pk(0.7978845608f, 0.7978845608f);
    const u64 GH  = pk(0.5f, 0.5f);

    // ---- phase 1: f = feat + gelu(LN(xyz_c @ W + b)) — no reduction, packed
#pragma unroll
    for (int i = 0; i < (HALO + 7) / 8; i++) {
        const int j  = warp + 8 * i;
        if (j >= HALO) continue;
        const int gr = r0 - 1 + j;
        if (gr < 0 || gr >= NPTS) continue;

        const float4 fa = *(const float4*)&feat[(size_t)gr * CH + c0];
        const float4 fb = *(const float4*)&feat[(size_t)gr * CH + c1];

        int seg = 0;
#pragma unroll
        for (int b = 1; b < NB; b++) seg += (gr >= s_off[b]);
        const float xc = coord[(size_t)3 * gr + 0] - s_mean[seg][0];
        const float yc = coord[(size_t)3 * gr + 1] - s_mean[seg][1];
        const float zc = coord[(size_t)3 * gr + 2] - s_mean[seg][2];

        float var = s_q[9];
        var += xc * fmaf(s_q[0], xc, fmaf(s_q[3], yc, fmaf(s_q[4], zc, s_q[6])));
        var += yc * fmaf(s_q[1], yc, fmaf(s_q[5], zc, s_q[7]));
        var += zc * fmaf(s_q[2], zc, s_q[8]);
        const float rstd = rsqrtf(var + EPSV);

        const u64 xc2 = pk(xc, xc), yc2 = pk(yc, yc), zc2 = pk(zc, zc);
        const u64 rs2 = pk(rstd, rstd);
        const u64 fv2[4] = {pk(fa.x, fa.y), pk(fa.z, fa.w), pk(fb.x, fb.y), pk(fb.z, fb.w)};

        float o8[8];
#pragma unroll
        for (int p = 0; p < 4; p++) {
            const u64 lin2 = fma2(xc2, cwx2[p], fma2(yc2, cwy2[p], fma2(zc2, cwz2[p], cbv2[p])));
            const u64 t2   = fma2(lin2, rs2, bb2[p]);
            // packed tanh-GELU (tanh itself scalar MUFU)
            const u64 tt2 = mul2(t2, t2);
            const u64 u2  = mul2(t2, fma2(GC0, tt2, GC1));
            float ua, ub; upk(u2, ua, ub);
            const u64 th2 = pk(tanh_a(ua), tanh_a(ub));
            const u64 hx2 = mul2(t2, GH);
            const u64 o2  = add2(fv2[p], fma2(hx2, th2, hx2));
            upk(o2, o8[2 * p], o8[2 * p + 1]);
        }
        *(float4*)&sf[j][c0] = make_float4(o8[0], o8[1], o8[2], o8[3]);
        *(float4*)&sf[j][c1] = make_float4(o8[4], o8[5], o8[6], o8[7]);
    }
    __syncthreads();

    // ---- phase-2 params packed
    u64 wc02[4], wc12[4], wc22[4], bc2[4], g2v2[4], be2v2[4];
    {
        float wc0[8], wc1[8], wc2[8];
#pragma unroll
        for (int k = 0; k < 8; k++) {
            const int ch = (k < 4) ? (c0 + k) : (c1 + k - 4);
            wc0[k] = w_conv[ch * 3 + 0];
            wc1[k] = w_conv[ch * 3 + 1];
            wc2[k] = w_conv[ch * 3 + 2];
        }
        const float4 b0 = *(const float4*)&b_conv[c0], b1 = *(const float4*)&b_conv[c1];
        const float4 g0 = *(const float4*)&g2[c0],     g1v4 = *(const float4*)&g2[c1];
        const float4 e0 = *(const float4*)&be2[c0],    e1 = *(const float4*)&be2[c1];
#pragma unroll
        for (int p = 0; p < 4; p++) {
            wc02[p] = pk(wc0[2 * p], wc0[2 * p + 1]);
            wc12[p] = pk(wc1[2 * p], wc1[2 * p + 1]);
            wc22[p] = pk(wc2[2 * p], wc2[2 * p + 1]);
        }
        bc2[0]   = pk(b0.x, b0.y); bc2[1]   = pk(b0.z, b0.w); bc2[2]   = pk(b1.x, b1.y); bc2[3]   = pk(b1.z, b1.w);
        g2v2[0]  = pk(g0.x, g0.y); g2v2[1]  = pk(g0.z, g0.w); g2v2[2]  = pk(g1v4.x, g1v4.y); g2v2[3] = pk(g1v4.z, g1v4.w);
        be2v2[0] = pk(e0.x, e0.y); be2v2[1] = pk(e0.z, e0.w); be2v2[2] = pk(e1.x, e1.y); be2v2[3] = pk(e1.z, e1.w);
    }

    // ---- phase 2: out = LN(feat + depthwise_conv(f)) — strided rows (ILP), packed
#pragma unroll
    for (int i = 0; i < ROWS / 8; i++) {
        const int j = warp + 8 * i;
        const int n = r0 + j;

        const float4 fa = *(const float4*)&feat[(size_t)n * CH + c0];
        const float4 fb = *(const float4*)&feat[(size_t)n * CH + c1];

        int seg = 0;
#pragma unroll
        for (int b = 1; b < NB; b++) seg += (n >= s_off[b]);
        const bool pok = (n - 1) >= s_off[seg];
        const bool nok = (n + 1) <  s_off[seg + 1];

        float4 p0 = *(const float4*)&sf[j][c0];
        float4 p1 = *(const float4*)&sf[j][c1];
        const float4 m0 = *(const float4*)&sf[j + 1][c0];
        const float4 m1 = *(const float4*)&sf[j + 1][c1];
        float4 q0 = *(const float4*)&sf[j + 2][c0];
        float4 q1 = *(const float4*)&sf[j + 2][c1];
        if (!pok) p0 = p1 = make_float4(0.f, 0.f, 0.f, 0.f);
        if (!nok) q0 = q1 = make_float4(0.f, 0.f, 0.f, 0.f);

        const u64 fv2[4] = {pk(fa.x, fa.y), pk(fa.z, fa.w), pk(fb.x, fb.y), pk(fb.z, fb.w)};
        const u64 fp2[4] = {pk(p0.x, p0.y), pk(p0.z, p0.w), pk(p1.x, p1.y), pk(p1.z, p1.w)};
        const u64 fc2[4] = {pk(m0.x, m0.y), pk(m0.z, m0.w), pk(m1.x, m1.y), pk(m1.z, m1.w)};
        const u64 fn2[4] = {pk(q0.x, q0.y), pk(q0.z, q0.w), pk(q1.x, q1.y), pk(q1.z, q1.w)};

        u64 y2[4];
        u64 sacc = pk(0.f, 0.f), s2acc = pk(0.f, 0.f);
#pragma unroll
        for (int p = 0; p < 4; p++) {
            const u64 conv2 = fma2(fp2[p], wc02[p], fma2(fc2[p], wc12[p], fma2(fn2[p], wc22[p], bc2[p])));
            const u64 v2 = add2(fv2[p], conv2);
            y2[p] = v2;
            sacc  = add2(sacc, v2);
            s2acc = fma2(v2, v2, s2acc);
        }
        float sa, sb, s2a, s2b;
        upk(sacc, sa, sb); upk(s2acc, s2a, s2b);
        float s = sa + sb, s2 = s2a + s2b;
        warp_sum2(s, s2);
        const float mu   = s * (1.f / CH);
        const float rstd = rsqrtf(fmaf(-mu, mu, s2 * (1.f / CH)) + EPSV);

        const u64 rs2  = pk(rstd, rstd);
        const u64 nmu2 = pk(-mu, -mu);
        float o8[8];
#pragma unroll
        for (int p = 0; p < 4; p++) {
            const u64 a2 = mul2(rs2, g2v2[p]);
            const u64 b2 = fma2(nmu2, a2, be2v2[p]);
            const u64 o2 = fma2(y2[p], a2, b2);
            upk(o2, o8[2 * p], o8[2 * p + 1]);
        }
        *(float4*)&out[(size_t)n * CH + c0] = make_float4(o8[0], o8[1], o8[2], o8[3]);
        *(float4*)&out[(size_t)n * CH + c1] = make_float4(o8[4], o8[5], o8[6], o8[7]);
    }
}

// ---------------------------------------------------------------- launch
extern "C" void kernel_launch(void* const* d_in, const int* in_sizes, int n_in,
                              void* d_out, int out_size) {
    const float* feat    = (const float*)d_in[0];
    const float* coord   = (const float*)d_in[1];
    const void*  lengths = d_in[2];
    const float* w_xyz   = (const float*)d_in[3];
    const float* b_xyz   = (const float*)d_in[4];
    const float* g1v     = (const float*)d_in[5];
    const float* be1     = (const float*)d_in[6];
    const float* w_conv  = (const float*)d_in[7];
    const float* b_conv  = (const float*)d_in[8];
    const float* g2vv    = (const float*)d_in[9];
    const float* be2     = (const float*)d_in[10];
    float* out = (float*)d_out;

    k_pre<<<NB * MCHUNK + 1, 256>>>(lengths, coord, w_xyz, b_xyz, g1v);
    k_main<<<NPTS / ROWS, 256>>>(feat, coord, be1, w_conv, b_conv, g2vv, be2, out);
}